// round 15
// baseline (speedup 1.0000x reference)
#include <cuda_runtime.h>
#include <cuda_fp16.h>
#include <cstdint>
#include <math.h>

#define NN 8192
#define IN_F 128
#define OUT_F 64
#define ALPHA 0.2f
#define LOG2E 1.4426950408889634f
#define NCH 64             // 32-col chunks over a 2048-col quarter
#define SBCH 8             // chunks per B superblock (256 cols)
#define SBN (NCH / SBCH)
#define BPITCH 528         // B smem row pitch -> 16B rotation, conflict-free
#define BBYTES (64 * BPITCH)
#define SPITCH 80          // score tile pitch -> 16B rotation, conflict-free
#define SWARP (2 * 16 * SPITCH)      // per-warp double-buffered score tile
#define SMEMT (2 * BBYTES + 8 * SWARP)   // 88064 B -> 2 CTAs/SM
#define NCTA 256

// ---------------- device scratch (allocation-free rule) ----------------
__device__ float  g_s1[NN];
__device__ float  g_s2[NN];
__device__ float  g_M;
__device__ __half g_hT[(size_t)OUT_F * NN];     // H^T fp16, [f][j]
__device__ float  g_num[(size_t)4 * NN * OUT_F];
__device__ float  g_den[4 * NN];
__device__ unsigned int g_arrive;               // grid barrier (reset by k_max)

// ---------------------------------------------------------------------------
// Kernel A: h = feat @ W^T ; s1/s2 row scores ; g_hT = fp16(h)^T
// ---------------------------------------------------------------------------
__global__ __launch_bounds__(1024) void k_proj(const float* __restrict__ feat,
                                               const float* __restrict__ W,
                                               const float* __restrict__ a) {
    __shared__ float Ws[OUT_F][IN_F + 4];
    __shared__ float Fs[16][IN_F];
    __shared__ float red1[32], red2[32];
    __shared__ __half Ts[OUT_F][18];

    int tid = threadIdx.x;
    int i0  = blockIdx.x * 16;

    for (int t = tid; t < OUT_F * IN_F; t += 1024)
        Ws[t / IN_F][t % IN_F] = W[t];
    for (int t = tid; t < 16 * IN_F; t += 1024)
        Fs[t / IN_F][t % IN_F] = feat[(size_t)(i0 + t / IN_F) * IN_F + (t % IN_F)];
    __syncthreads();

    int f = tid & 63;
    int r = tid >> 6;
    float acc = 0.f;
#pragma unroll
    for (int k = 0; k < IN_F; k += 4) {
        float4 fv = *(const float4*)&Fs[r][k];
        float4 wv = *(const float4*)&Ws[f][k];
        acc += fv.x * wv.x + fv.y * wv.y + fv.z * wv.z + fv.w * wv.w;
    }

    Ts[f][r] = __float2half(acc);

    float t1 = acc * a[f];
    float t2 = acc * a[OUT_F + f];
#pragma unroll
    for (int off = 16; off; off >>= 1) {
        t1 += __shfl_xor_sync(0xffffffffu, t1, off);
        t2 += __shfl_xor_sync(0xffffffffu, t2, off);
    }
    int w = tid >> 5;
    if ((tid & 31) == 0) { red1[w] = t1; red2[w] = t2; }
    __syncthreads();
    if (tid < 16) {
        g_s1[i0 + tid] = red1[2 * tid] + red1[2 * tid + 1];
        g_s2[i0 + tid] = red2[2 * tid] + red2[2 * tid + 1];
    }
    if (tid < 512) {
        int ff = tid >> 3, u = tid & 7;
        __half2 pk = __halves2half2(Ts[ff][2 * u], Ts[ff][2 * u + 1]);
        *(__half2*)&g_hT[(size_t)ff * NN + i0 + 2 * u] = pk;
    }
}

// ---------------------------------------------------------------------------
// Kernel B: g_M = max_j s2[j]  + resets the k_main grid barrier counter
// ---------------------------------------------------------------------------
__global__ __launch_bounds__(256) void k_max() {
    __shared__ float red[8];
    int tid = threadIdx.x;
    if (tid == 0) g_arrive = 0;      // fresh barrier each replay
    float m = -1e30f;
    for (int i = tid; i < NN; i += 256) m = fmaxf(m, g_s2[i]);
#pragma unroll
    for (int off = 16; off; off >>= 1)
        m = fmaxf(m, __shfl_xor_sync(0xffffffffu, m, off));
    if ((tid & 31) == 0) red[tid >> 5] = m;
    __syncthreads();
    if (tid == 0) {
        float mm = red[0];
#pragma unroll
        for (int i = 1; i < 8; i++) mm = fmaxf(mm, red[i]);
        g_M = mm;
    }
}

// ---------------------------------------------------------------------------
// Main kernel. 256 CTAs (64 row-tiles x 4 quarters) x 256 threads, 2 CTAs/SM
// (exactly one wave -> grid-wide arrival barrier is deadlock-free).
// After the barrier, each CTA finalizes its own 32 output rows (fused k_fin).
// ---------------------------------------------------------------------------
struct ChunkBuf {
    float4 G[4];
    float4 S[4];
    float4 Z;
};

__device__ __forceinline__ void load_chunk(const float* __restrict__ gp0,
                                           const float* __restrict__ sp0,
                                           const float* __restrict__ s2p,
                                           int c, ChunkBuf& b) {
    size_t off = (size_t)c * 32;
#pragma unroll
    for (int i = 0; i < 4; i++) {
        b.G[i] = __ldcs((const float4*)(gp0 + off + (size_t)(4 * i) * NN));
        b.S[i] = __ldcs((const float4*)(sp0 + off + (size_t)(4 * i) * NN));
    }
    b.Z = *(const float4*)(s2p + off);
}

__device__ __forceinline__ void mma16816(float* d, const uint32_t* a,
                                         uint32_t b0, uint32_t b1) {
    asm volatile(
        "mma.sync.aligned.m16n8k16.row.col.f32.f16.f16.f32 "
        "{%0,%1,%2,%3},{%4,%5,%6,%7},{%8,%9},{%0,%1,%2,%3};"
        : "+f"(d[0]), "+f"(d[1]), "+f"(d[2]), "+f"(d[3])
        : "r"(a[0]), "r"(a[1]), "r"(a[2]), "r"(a[3]), "r"(b0), "r"(b1));
}

__device__ __forceinline__ void ldsm_x4(uint32_t* r, uint32_t addr) {
    asm volatile(
        "ldmatrix.sync.aligned.m8n8.x4.shared.b16 {%0,%1,%2,%3}, [%4];"
        : "=r"(r[0]), "=r"(r[1]), "=r"(r[2]), "=r"(r[3]) : "r"(addr));
}

__device__ __forceinline__ void proc_chunk(int c, int cn, int par,
                                           ChunkBuf& cur, ChunkBuf& nxt,
                                           const float* gp0, const float* sp0,
                                           const float* s2p,
                                           uint32_t sts0, uint32_t lda0, uint32_t ldb,
                                           const float (&s1v)[4], const float (&bnv)[4],
                                           float (&dloc)[4], float (&acc)[8][4]) {
    // 1. prefetch next chunk's adjacency (coalesced LDG.128)
    load_chunk(gp0, sp0, s2p, cn, nxt);

    uint32_t bufo = (uint32_t)par * (16 * SPITCH);

    // 2. scores in coalesced layout (4 rows x 4 cols per thread) -> smem
    __half2 dh[4];
#pragma unroll
    for (int i = 0; i < 4; i++) {
        float4 g = cur.G[i], s = cur.S[i];
        float clx = (g.x + s.x) * LOG2E;
        float cly = (g.y + s.y) * LOG2E;
        float clz = (g.z + s.z) * LOG2E;
        float clw = (g.w + s.w) * LOG2E;
        float s1 = s1v[i], bn = bnv[i];
        float x0 = s1 + cur.Z.x, x1 = s1 + cur.Z.y;
        float x2 = s1 + cur.Z.z, x3 = s1 + cur.Z.w;
        float l0 = fmaxf(x0, ALPHA * x0), l1 = fmaxf(x1, ALPHA * x1);
        float l2 = fmaxf(x2, ALPHA * x2), l3 = fmaxf(x3, ALPHA * x3);
        float p0 = (clx > 0.f) ? exp2f(fmaf(l0, clx, -bn)) : 0.f;
        float p1 = (cly > 0.f) ? exp2f(fmaf(l1, cly, -bn)) : 0.f;
        float p2 = (clz > 0.f) ? exp2f(fmaf(l2, clz, -bn)) : 0.f;
        float p3 = (clw > 0.f) ? exp2f(fmaf(l3, clw, -bn)) : 0.f;
        __half2 lo = __floats2half2_rn(p0, p1);
        __half2 hi = __floats2half2_rn(p2, p3);
        dh[i] = __hadd2(lo, hi);
        asm volatile("st.shared.v2.b32 [%0], {%1,%2};"
                     :: "r"(sts0 + bufo + (uint32_t)(4 * i) * SPITCH),
                        "r"(*(uint32_t*)&lo), "r"(*(uint32_t*)&hi));
    }

    __syncwarp();

    // 3. A-frags first (LDSM latency covered by the dloc arithmetic below)
    uint32_t af[2][4];
    uint32_t la = lda0 + bufo;
    ldsm_x4(af[0], la);
    ldsm_x4(af[1], la + 32);

#pragma unroll
    for (int i = 0; i < 4; i++) {
        float2 d = __half22float2(dh[i]);
        dloc[i] += d.x + d.y;
    }

    // 4. B-frag stream, depth-1 double buffered
    uint32_t bb = ldb + (uint32_t)(c & (SBCH - 1)) * 64;
    uint32_t breg[2][4];
    ldsm_x4(breg[0], bb);
#pragma unroll
    for (int idx = 0; idx < 8; idx++) {
        if (idx < 7) {
            int nid = idx + 1;
            ldsm_x4(breg[nid & 1],
                    bb + (uint32_t)(nid & 3) * 16 * BPITCH + (uint32_t)(nid >> 2) * 32);
        }
        int kk = idx >> 2, t = idx & 3;
        mma16816(acc[2 * t],     af[kk], breg[idx & 1][0], breg[idx & 1][1]);
        mma16816(acc[2 * t + 1], af[kk], breg[idx & 1][2], breg[idx & 1][3]);
    }
}

__global__ __launch_bounds__(256, 2) void k_main(const float* __restrict__ geo,
                                                 const float* __restrict__ sem,
                                                 float* __restrict__ out) {
    extern __shared__ __align__(16) char smem[];

    int tid = threadIdx.x, lane = tid & 31, w = tid >> 5;
    int rb = blockIdx.x >> 2, q = blockIdx.x & 3;
    int i0 = rb * 128, jbase = q * 2048;

    int subrow = lane >> 3, colseg = (lane & 7) * 4;

    const float* gp0 = geo + (size_t)(i0 + 16 * w + subrow) * NN + jbase + colseg;
    const float* sp0 = sem + (size_t)(i0 + 16 * w + subrow) * NN + jbase + colseg;
    const float* s2p = g_s2 + jbase + colseg;

    float Mv = g_M;
    float s1v[4], bnv[4];
#pragma unroll
    for (int i = 0; i < 4; i++) {
        s1v[i] = g_s1[i0 + 16 * w + 4 * i + subrow];
        bnv[i] = fmaxf(0.f, 2.f * (s1v[i] + Mv)) * LOG2E;
    }

    uint32_t smem0;
    asm("{ .reg .u64 t; cvta.to.shared.u64 t, %1; cvt.u32.u64 %0, t; }"
        : "=r"(smem0) : "l"(smem));
    uint32_t bbase = smem0;
    uint32_t sbuf  = smem0 + 2 * BBYTES + w * SWARP;

    uint32_t sts0 = sbuf + (uint32_t)subrow * SPITCH + (uint32_t)colseg * 2;
    uint32_t lda0 = sbuf + (uint32_t)(lane & 15) * SPITCH + (uint32_t)(lane >> 4) * 16;
    int ldrow = ((lane >> 4) & 1) * 8 + (lane & 7);
    int ldcol = ((lane >> 3) & 1) * 16;
    uint32_t ldb0 = bbase + (uint32_t)ldrow * BPITCH + ldcol;

    // B staging map
    int srow = tid >> 5, sseg = tid & 31;
    const __half* bsrc = g_hT + (size_t)srow * NN + jbase + sseg * 8;
    uint32_t bdst = bbase + (uint32_t)srow * BPITCH + sseg * 16;

    float acc[8][4];
#pragma unroll
    for (int i = 0; i < 8; i++)
#pragma unroll
        for (int j = 0; j < 4; j++) acc[i][j] = 0.f;
    float dloc[4] = {0.f, 0.f, 0.f, 0.f};

    // prologue: stage B superblock 0
#pragma unroll
    for (int p = 0; p < 8; p++)
        asm volatile("cp.async.cg.shared.global [%0], [%1], 16;"
                     :: "r"(bdst + (uint32_t)(8 * p) * BPITCH),
                        "l"(bsrc + (size_t)(8 * p) * NN));
    asm volatile("cp.async.commit_group;");
    asm volatile("cp.async.wait_group 0;");

    // prologue: warp w starts at its rotated chunk
    ChunkBuf A0, A1;
    load_chunk(gp0, sp0, s2p, w & 7, A0);
    __syncthreads();

    for (int sb = 0; sb < SBN; sb++) {
        if (sb + 1 < SBN) {
            int jblk = (sb + 1) * (SBCH * 32);
            uint32_t bd = bdst + (uint32_t)((sb + 1) & 1) * BBYTES;
#pragma unroll
            for (int p = 0; p < 8; p++)
                asm volatile("cp.async.cg.shared.global [%0], [%1], 16;"
                             :: "r"(bd + (uint32_t)(8 * p) * BPITCH),
                                "l"(bsrc + (size_t)(8 * p) * NN + jblk));
            asm volatile("cp.async.commit_group;");
        }

        uint32_t ldb = ldb0 + (uint32_t)(sb & 1) * BBYTES;
#pragma unroll
        for (int cc = 0; cc < SBCH; cc++) {
            int c = sb * SBCH + ((cc + w) & 7);
            int ncc = cc + 1, nsb = sb;
            if (ncc == SBCH) { ncc = 0; nsb = sb + 1; }
            int cn = (nsb < SBN) ? (nsb * SBCH + ((ncc + w) & 7)) : 0;
            if (cc & 1)
                proc_chunk(c, cn, 1, A1, A0, gp0, sp0, s2p, sts0, lda0, ldb,
                           s1v, bnv, dloc, acc);
            else
                proc_chunk(c, cn, 0, A0, A1, gp0, sp0, s2p, sts0, lda0, ldb,
                           s1v, bnv, dloc, acc);
        }

        asm volatile("cp.async.wait_group 0;");
        __syncthreads();
    }

    // ---- per-CTA partial epilogue ----
#pragma unroll
    for (int i = 0; i < 4; i++) {
        float v = dloc[i];
        v += __shfl_xor_sync(0xffffffffu, v, 1);
        v += __shfl_xor_sync(0xffffffffu, v, 2);
        v += __shfl_xor_sync(0xffffffffu, v, 4);
        dloc[i] = v;
    }
    if ((lane & 7) == 0) {
#pragma unroll
        for (int i = 0; i < 4; i++)
            g_den[q * NN + i0 + 16 * w + 4 * i + subrow] = dloc[i];
    }

    {
        int r = lane >> 2, tg = lane & 3;
        int row0 = i0 + 16 * w + r;
        float* dst0 = g_num + ((size_t)q * NN + row0) * OUT_F;
        float* dst1 = g_num + ((size_t)q * NN + row0 + 8) * OUT_F;
#pragma unroll
        for (int t = 0; t < 8; t++) {
            int n0 = 8 * t + 2 * tg;
            *(float2*)(dst0 + n0) = make_float2(acc[t][0], acc[t][1]);
            *(float2*)(dst1 + n0) = make_float2(acc[t][2], acc[t][3]);
        }
    }

    // ---- grid-wide barrier (single wave: 256 CTAs, occ 2 on 148 SMs) ----
    __threadfence();
    __syncthreads();
    if (tid == 0) {
        atomicAdd(&g_arrive, 1u);
        while (*(volatile unsigned int*)&g_arrive < NCTA) __nanosleep(64);
        __threadfence();
    }
    __syncthreads();

    // ---- fused finalize: this CTA owns 32 output rows ----
    {
        int row = blockIdx.x * 32 + (tid >> 3);
        int seg = tid & 7;                       // 8 floats per thread
        float den = __ldcg(&g_den[row]) + __ldcg(&g_den[NN + row]) +
                    __ldcg(&g_den[2 * NN + row]) + __ldcg(&g_den[3 * NN + row]);
        float inv = 1.0f / den;
        const float* n0 = g_num + (size_t)row * OUT_F + seg * 8;
        const float* n1 = n0 + (size_t)NN * OUT_F;
        const float* n2 = n1 + (size_t)NN * OUT_F;
        const float* n3 = n2 + (size_t)NN * OUT_F;
        float* op = out + (size_t)row * OUT_F + seg * 8;
#pragma unroll
        for (int h = 0; h < 2; h++) {
            float4 a0 = __ldcg((const float4*)(n0 + 4 * h));
            float4 a1 = __ldcg((const float4*)(n1 + 4 * h));
            float4 a2 = __ldcg((const float4*)(n2 + 4 * h));
            float4 a3 = __ldcg((const float4*)(n3 + 4 * h));
            float4 o;
            float v;
            v = (a0.x + a1.x + a2.x + a3.x) * inv; o.x = (v > 0.f) ? v : expm1f(v);
            v = (a0.y + a1.y + a2.y + a3.y) * inv; o.y = (v > 0.f) ? v : expm1f(v);
            v = (a0.z + a1.z + a2.z + a3.z) * inv; o.z = (v > 0.f) ? v : expm1f(v);
            v = (a0.w + a1.w + a2.w + a3.w) * inv; o.w = (v > 0.f) ? v : expm1f(v);
            *(float4*)(op + 4 * h) = o;
        }
    }
}

// ---------------------------------------------------------------------------
extern "C" void kernel_launch(void* const* d_in, const int* in_sizes, int n_in,
                              void* d_out, int out_size) {
    const float* geo  = (const float*)d_in[0];
    const float* sem  = (const float*)d_in[1];
    const float* feat = (const float*)d_in[2];
    const float* W    = (const float*)d_in[3];
    const float* a    = (const float*)d_in[4];
    float* out = (float*)d_out;

    cudaFuncSetAttribute(k_main, cudaFuncAttributeMaxDynamicSharedMemorySize, SMEMT);

    k_proj<<<NN / 16, 1024>>>(feat, W, a);
    k_max<<<1, 256>>>();
    k_main<<<NCTA, 256, SMEMT>>>(geo, sem, out);
}

// round 16
// speedup vs baseline: 1.0984x; 1.0984x over previous
#include <cuda_runtime.h>
#include <cuda_fp16.h>
#include <cstdint>
#include <math.h>

#define NN 8192
#define IN_F 128
#define OUT_F 64
#define ALPHA 0.2f
#define LOG2E 1.4426950408889634f
#define NCH 64             // 32-col chunks over a 2048-col quarter
#define SBCH 8             // chunks per B superblock (256 cols)
#define SBN (NCH / SBCH)
#define BPITCH 528         // B smem row pitch -> 16B rotation, conflict-free
#define BBYTES (64 * BPITCH)
#define SPITCH 80          // score tile pitch -> 16B rotation, conflict-free
#define SWARP (2 * 16 * SPITCH)      // per-warp double-buffered score tile
#define SMEMT (2 * BBYTES + 8 * SWARP)   // 88064 B -> 2 CTAs/SM
#define WPITCH 68
#define PROJ_SMEM ((128 * WPITCH + 64 * IN_F) * 4)   // 67584 B

// ---------------- device scratch (allocation-free rule) ----------------
__device__ float  g_s1[NN];
__device__ float  g_s2[NN];
__device__ float  g_M;
__device__ __half g_hT[(size_t)OUT_F * NN];     // H^T fp16, [f][j]
__device__ float  g_num[(size_t)4 * NN * OUT_F];
__device__ float  g_den[4 * NN];

// ---------------------------------------------------------------------------
// Kernel A (v2): 4x4 register-blocked h = feat @ W^T ; s1/s2 ; g_hT = fp16(h)^T
// 128 CTAs x 256 threads, 64 rows/CTA. W transposed in smem (pitch 68,
// conflict-free reads AND writes). 0.125 LDS per FMA.
// ---------------------------------------------------------------------------
__global__ __launch_bounds__(256) void k_proj(const float* __restrict__ feat,
                                              const float* __restrict__ W,
                                              const float* __restrict__ a) {
    extern __shared__ float ps[];
    float* Wt = ps;                   // [128][WPITCH]
    float* Fs = ps + 128 * WPITCH;    // [64][128]

    int tid = threadIdx.x;
    int i0  = blockIdx.x * 64;

    // ---- stage W transposed: Wt[k][f] = W[f][k] ----
#pragma unroll
    for (int i = 0; i < 2; i++) {
        int idx = tid + 256 * i;
        int f = idx & 63, kc = idx >> 6;       // kc in 0..7
#pragma unroll
        for (int t = 0; t < 4; t++) {
            int k4 = kc * 4 + t;               // float4 index within row
            float4 v = *(const float4*)(W + (size_t)f * IN_F + 4 * k4);
            Wt[(4 * k4 + 0) * WPITCH + f] = v.x;   // STS.32, bank = f -> conflict-free
            Wt[(4 * k4 + 1) * WPITCH + f] = v.y;
            Wt[(4 * k4 + 2) * WPITCH + f] = v.z;
            Wt[(4 * k4 + 3) * WPITCH + f] = v.w;
        }
    }
    // ---- stage F (coalesced) ----
#pragma unroll
    for (int i = 0; i < 8; i++) {
        int idx = tid + 256 * i;
        int r = idx >> 5, kq = idx & 31;
        *(float4*)(Fs + r * IN_F + 4 * kq) =
            *(const float4*)(feat + (size_t)(i0 + r) * IN_F + 4 * kq);
    }
    __syncthreads();

    int fg = tid & 15, rowg = tid >> 4;
    int f0 = 4 * fg, r0 = 4 * rowg;

    float acc[4][4];
#pragma unroll
    for (int i = 0; i < 4; i++)
#pragma unroll
        for (int j = 0; j < 4; j++) acc[i][j] = 0.f;

#pragma unroll 8
    for (int kq = 0; kq < 32; kq++) {
        float4 fv[4], wv[4];
#pragma unroll
        for (int i = 0; i < 4; i++)
            fv[i] = *(const float4*)(Fs + (r0 + i) * IN_F + 4 * kq);
#pragma unroll
        for (int t = 0; t < 4; t++)
            wv[t] = *(const float4*)(Wt + (4 * kq + t) * WPITCH + f0);
#pragma unroll
        for (int i = 0; i < 4; i++) {
            float fx = fv[i].x, fy = fv[i].y, fz = fv[i].z, fw = fv[i].w;
            acc[i][0] = fmaf(fx, wv[0].x, fmaf(fy, wv[1].x, fmaf(fz, wv[2].x, fmaf(fw, wv[3].x, acc[i][0]))));
            acc[i][1] = fmaf(fx, wv[0].y, fmaf(fy, wv[1].y, fmaf(fz, wv[2].y, fmaf(fw, wv[3].y, acc[i][1]))));
            acc[i][2] = fmaf(fx, wv[0].z, fmaf(fy, wv[1].z, fmaf(fz, wv[2].z, fmaf(fw, wv[3].z, acc[i][2]))));
            acc[i][3] = fmaf(fx, wv[0].w, fmaf(fy, wv[1].w, fmaf(fz, wv[2].w, fmaf(fw, wv[3].w, acc[i][3]))));
        }
    }

    // ---- s1/s2: per-thread partial dot with a, shfl-reduce over fg lanes ----
    float a1v[4], a2v[4];
#pragma unroll
    for (int j = 0; j < 4; j++) {
        a1v[j] = a[f0 + j];
        a2v[j] = a[OUT_F + f0 + j];
    }
    float s1p[4], s2p[4];
#pragma unroll
    for (int i = 0; i < 4; i++) {
        s1p[i] = acc[i][0] * a1v[0] + acc[i][1] * a1v[1] +
                 acc[i][2] * a1v[2] + acc[i][3] * a1v[3];
        s2p[i] = acc[i][0] * a2v[0] + acc[i][1] * a2v[1] +
                 acc[i][2] * a2v[2] + acc[i][3] * a2v[3];
    }
#pragma unroll
    for (int m = 1; m <= 8; m <<= 1) {
#pragma unroll
        for (int i = 0; i < 4; i++) {
            s1p[i] += __shfl_xor_sync(0xffffffffu, s1p[i], m);
            s2p[i] += __shfl_xor_sync(0xffffffffu, s2p[i], m);
        }
    }
    if (fg == 0) {
#pragma unroll
        for (int i = 0; i < 4; i++) {
            g_s1[i0 + r0 + i] = s1p[i];
            g_s2[i0 + r0 + i] = s2p[i];
        }
    }

    // ---- h -> g_hT (fp16, transposed) ----
#pragma unroll
    for (int j = 0; j < 4; j++) {
        __half2 h01 = __floats2half2_rn(acc[0][j], acc[1][j]);
        __half2 h23 = __floats2half2_rn(acc[2][j], acc[3][j]);
        *(__half2*)&g_hT[(size_t)(f0 + j) * NN + i0 + r0]     = h01;
        *(__half2*)&g_hT[(size_t)(f0 + j) * NN + i0 + r0 + 2] = h23;
    }
}

// ---------------------------------------------------------------------------
// Kernel B: g_M = max_j s2[j]
// ---------------------------------------------------------------------------
__global__ __launch_bounds__(256) void k_max() {
    __shared__ float red[8];
    int tid = threadIdx.x;
    float m = -1e30f;
    for (int i = tid; i < NN; i += 256) m = fmaxf(m, g_s2[i]);
#pragma unroll
    for (int off = 16; off; off >>= 1)
        m = fmaxf(m, __shfl_xor_sync(0xffffffffu, m, off));
    if ((tid & 31) == 0) red[tid >> 5] = m;
    __syncthreads();
    if (tid == 0) {
        float mm = red[0];
#pragma unroll
        for (int i = 1; i < 8; i++) mm = fmaxf(mm, red[i]);
        g_M = mm;
    }
}

// ---------------------------------------------------------------------------
// Main kernel. 256 CTAs (64 row-tiles x 4 quarters) x 256 threads, 2 CTAs/SM.
// ---------------------------------------------------------------------------
struct ChunkBuf {
    float4 G[4];
    float4 S[4];
    float4 Z;
};

__device__ __forceinline__ void load_chunk(const float* __restrict__ gp0,
                                           const float* __restrict__ sp0,
                                           const float* __restrict__ s2p,
                                           int c, ChunkBuf& b) {
    size_t off = (size_t)c * 32;
#pragma unroll
    for (int i = 0; i < 4; i++) {
        b.G[i] = __ldcs((const float4*)(gp0 + off + (size_t)(4 * i) * NN));
        b.S[i] = __ldcs((const float4*)(sp0 + off + (size_t)(4 * i) * NN));
    }
    b.Z = *(const float4*)(s2p + off);
}

__device__ __forceinline__ void mma16816(float* d, const uint32_t* a,
                                         uint32_t b0, uint32_t b1) {
    asm volatile(
        "mma.sync.aligned.m16n8k16.row.col.f32.f16.f16.f32 "
        "{%0,%1,%2,%3},{%4,%5,%6,%7},{%8,%9},{%0,%1,%2,%3};"
        : "+f"(d[0]), "+f"(d[1]), "+f"(d[2]), "+f"(d[3])
        : "r"(a[0]), "r"(a[1]), "r"(a[2]), "r"(a[3]), "r"(b0), "r"(b1));
}

__device__ __forceinline__ void ldsm_x4(uint32_t* r, uint32_t addr) {
    asm volatile(
        "ldmatrix.sync.aligned.m8n8.x4.shared.b16 {%0,%1,%2,%3}, [%4];"
        : "=r"(r[0]), "=r"(r[1]), "=r"(r[2]), "=r"(r[3]) : "r"(addr));
}

__device__ __forceinline__ void proc_chunk(int c, int cn, int par,
                                           ChunkBuf& cur, ChunkBuf& nxt,
                                           const float* gp0, const float* sp0,
                                           const float* s2p,
                                           uint32_t sts0, uint32_t lda0, uint32_t ldb,
                                           const float (&s1v)[4], const float (&bnv)[4],
                                           float (&dloc)[4], float (&acc)[8][4]) {
    // 1. prefetch next chunk's adjacency (coalesced LDG.128)
    load_chunk(gp0, sp0, s2p, cn, nxt);

    uint32_t bufo = (uint32_t)par * (16 * SPITCH);

    // 2. scores in coalesced layout (4 rows x 4 cols per thread) -> smem
    __half2 dh[4];
#pragma unroll
    for (int i = 0; i < 4; i++) {
        float4 g = cur.G[i], s = cur.S[i];
        float clx = (g.x + s.x) * LOG2E;
        float cly = (g.y + s.y) * LOG2E;
        float clz = (g.z + s.z) * LOG2E;
        float clw = (g.w + s.w) * LOG2E;
        float s1 = s1v[i], bn = bnv[i];
        float x0 = s1 + cur.Z.x, x1 = s1 + cur.Z.y;
        float x2 = s1 + cur.Z.z, x3 = s1 + cur.Z.w;
        float l0 = fmaxf(x0, ALPHA * x0), l1 = fmaxf(x1, ALPHA * x1);
        float l2 = fmaxf(x2, ALPHA * x2), l3 = fmaxf(x3, ALPHA * x3);
        float p0 = (clx > 0.f) ? exp2f(fmaf(l0, clx, -bn)) : 0.f;
        float p1 = (cly > 0.f) ? exp2f(fmaf(l1, cly, -bn)) : 0.f;
        float p2 = (clz > 0.f) ? exp2f(fmaf(l2, clz, -bn)) : 0.f;
        float p3 = (clw > 0.f) ? exp2f(fmaf(l3, clw, -bn)) : 0.f;
        __half2 lo = __floats2half2_rn(p0, p1);
        __half2 hi = __floats2half2_rn(p2, p3);
        dh[i] = __hadd2(lo, hi);
        asm volatile("st.shared.v2.b32 [%0], {%1,%2};"
                     :: "r"(sts0 + bufo + (uint32_t)(4 * i) * SPITCH),
                        "r"(*(uint32_t*)&lo), "r"(*(uint32_t*)&hi));
    }

    __syncwarp();

    // 3. A-frags first (LDSM latency covered by the dloc arithmetic below)
    uint32_t af[2][4];
    uint32_t la = lda0 + bufo;
    ldsm_x4(af[0], la);
    ldsm_x4(af[1], la + 32);

#pragma unroll
    for (int i = 0; i < 4; i++) {
        float2 d = __half22float2(dh[i]);
        dloc[i] += d.x + d.y;
    }

    // 4. B-frag stream, depth-1 double buffered
    uint32_t bb = ldb + (uint32_t)(c & (SBCH - 1)) * 64;
    uint32_t breg[2][4];
    ldsm_x4(breg[0], bb);
#pragma unroll
    for (int idx = 0; idx < 8; idx++) {
        if (idx < 7) {
            int nid = idx + 1;
            ldsm_x4(breg[nid & 1],
                    bb + (uint32_t)(nid & 3) * 16 * BPITCH + (uint32_t)(nid >> 2) * 32);
        }
        int kk = idx >> 2, t = idx & 3;
        mma16816(acc[2 * t],     af[kk], breg[idx & 1][0], breg[idx & 1][1]);
        mma16816(acc[2 * t + 1], af[kk], breg[idx & 1][2], breg[idx & 1][3]);
    }
}

__global__ __launch_bounds__(256, 2) void k_main(const float* __restrict__ geo,
                                                 const float* __restrict__ sem) {
    extern __shared__ __align__(16) char smem[];

    int tid = threadIdx.x, lane = tid & 31, w = tid >> 5;
    int rb = blockIdx.x >> 2, q = blockIdx.x & 3;
    int i0 = rb * 128, jbase = q * 2048;

    int subrow = lane >> 3, colseg = (lane & 7) * 4;

    const float* gp0 = geo + (size_t)(i0 + 16 * w + subrow) * NN + jbase + colseg;
    const float* sp0 = sem + (size_t)(i0 + 16 * w + subrow) * NN + jbase + colseg;
    const float* s2p = g_s2 + jbase + colseg;

    float Mv = g_M;
    float s1v[4], bnv[4];
#pragma unroll
    for (int i = 0; i < 4; i++) {
        s1v[i] = g_s1[i0 + 16 * w + 4 * i + subrow];
        bnv[i] = fmaxf(0.f, 2.f * (s1v[i] + Mv)) * LOG2E;
    }

    uint32_t smem0;
    asm("{ .reg .u64 t; cvta.to.shared.u64 t, %1; cvt.u32.u64 %0, t; }"
        : "=r"(smem0) : "l"(smem));
    uint32_t bbase = smem0;
    uint32_t sbuf  = smem0 + 2 * BBYTES + w * SWARP;

    uint32_t sts0 = sbuf + (uint32_t)subrow * SPITCH + (uint32_t)colseg * 2;
    uint32_t lda0 = sbuf + (uint32_t)(lane & 15) * SPITCH + (uint32_t)(lane >> 4) * 16;
    int ldrow = ((lane >> 4) & 1) * 8 + (lane & 7);
    int ldcol = ((lane >> 3) & 1) * 16;
    uint32_t ldb0 = bbase + (uint32_t)ldrow * BPITCH + ldcol;

    // B staging map
    int srow = tid >> 5, sseg = tid & 31;
    const __half* bsrc = g_hT + (size_t)srow * NN + jbase + sseg * 8;
    uint32_t bdst = bbase + (uint32_t)srow * BPITCH + sseg * 16;

    float acc[8][4];
#pragma unroll
    for (int i = 0; i < 8; i++)
#pragma unroll
        for (int j = 0; j < 4; j++) acc[i][j] = 0.f;
    float dloc[4] = {0.f, 0.f, 0.f, 0.f};

    // prologue: stage B superblock 0
#pragma unroll
    for (int p = 0; p < 8; p++)
        asm volatile("cp.async.cg.shared.global [%0], [%1], 16;"
                     :: "r"(bdst + (uint32_t)(8 * p) * BPITCH),
                        "l"(bsrc + (size_t)(8 * p) * NN));
    asm volatile("cp.async.commit_group;");
    asm volatile("cp.async.wait_group 0;");

    // prologue: warp w starts at its rotated chunk
    ChunkBuf A0, A1;
    load_chunk(gp0, sp0, s2p, w & 7, A0);
    __syncthreads();

    for (int sb = 0; sb < SBN; sb++) {
        if (sb + 1 < SBN) {
            int jblk = (sb + 1) * (SBCH * 32);
            uint32_t bd = bdst + (uint32_t)((sb + 1) & 1) * BBYTES;
#pragma unroll
            for (int p = 0; p < 8; p++)
                asm volatile("cp.async.cg.shared.global [%0], [%1], 16;"
                             :: "r"(bd + (uint32_t)(8 * p) * BPITCH),
                                "l"(bsrc + (size_t)(8 * p) * NN + jblk));
            asm volatile("cp.async.commit_group;");
        }

        uint32_t ldb = ldb0 + (uint32_t)(sb & 1) * BBYTES;
#pragma unroll
        for (int cc = 0; cc < SBCH; cc++) {
            int c = sb * SBCH + ((cc + w) & 7);
            int ncc = cc + 1, nsb = sb;
            if (ncc == SBCH) { ncc = 0; nsb = sb + 1; }
            int cn = (nsb < SBN) ? (nsb * SBCH + ((ncc + w) & 7)) : 0;
            if (cc & 1)
                proc_chunk(c, cn, 1, A1, A0, gp0, sp0, s2p, sts0, lda0, ldb,
                           s1v, bnv, dloc, acc);
            else
                proc_chunk(c, cn, 0, A0, A1, gp0, sp0, s2p, sts0, lda0, ldb,
                           s1v, bnv, dloc, acc);
        }

        asm volatile("cp.async.wait_group 0;");
        __syncthreads();
    }

    // ---- epilogue ----
#pragma unroll
    for (int i = 0; i < 4; i++) {
        float v = dloc[i];
        v += __shfl_xor_sync(0xffffffffu, v, 1);
        v += __shfl_xor_sync(0xffffffffu, v, 2);
        v += __shfl_xor_sync(0xffffffffu, v, 4);
        dloc[i] = v;
    }
    if ((lane & 7) == 0) {
#pragma unroll
        for (int i = 0; i < 4; i++)
            g_den[q * NN + i0 + 16 * w + 4 * i + subrow] = dloc[i];
    }

    // numerator partials: c-frag layout (r = lane>>2, tg = lane&3)
    int r = lane >> 2, tg = lane & 3;
    int row0 = i0 + 16 * w + r;
    float* dst0 = g_num + ((size_t)q * NN + row0) * OUT_F;
    float* dst1 = g_num + ((size_t)q * NN + row0 + 8) * OUT_F;
#pragma unroll
    for (int t = 0; t < 8; t++) {
        int n0 = 8 * t + 2 * tg;
        *(float2*)(dst0 + n0) = make_float2(acc[t][0], acc[t][1]);
        *(float2*)(dst1 + n0) = make_float2(acc[t][2], acc[t][3]);
    }
}

// ---------------------------------------------------------------------------
// Combine split-K partials: out = elu(sum(n)/sum(d))
// ---------------------------------------------------------------------------
__global__ __launch_bounds__(256) void k_fin(float* __restrict__ out) {
    int idx = blockIdx.x * 256 + threadIdx.x;     // 262144 threads
    int row = idx >> 5, qq = idx & 31;            // 32 threads/row, 2 floats
    float den = g_den[row] + g_den[NN + row] + g_den[2 * NN + row] + g_den[3 * NN + row];
    float inv = 1.0f / den;
    float2 n0 = *(const float2*)&g_num[(size_t)row * OUT_F + 2 * qq];
    float2 n1 = *(const float2*)&g_num[(size_t)(NN + row) * OUT_F + 2 * qq];
    float2 n2 = *(const float2*)&g_num[(size_t)(2 * NN + row) * OUT_F + 2 * qq];
    float2 n3 = *(const float2*)&g_num[(size_t)(3 * NN + row) * OUT_F + 2 * qq];
    float2 o;
    float v;
    v = (n0.x + n1.x + n2.x + n3.x) * inv; o.x = (v > 0.f) ? v : expm1f(v);
    v = (n0.y + n1.y + n2.y + n3.y) * inv; o.y = (v > 0.f) ? v : expm1f(v);
    *(float2*)&out[(size_t)row * OUT_F + 2 * qq] = o;
}

// ---------------------------------------------------------------------------
extern "C" void kernel_launch(void* const* d_in, const int* in_sizes, int n_in,
                              void* d_out, int out_size) {
    const float* geo  = (const float*)d_in[0];
    const float* sem  = (const float*)d_in[1];
    const float* feat = (const float*)d_in[2];
    const float* W    = (const float*)d_in[3];
    const float* a    = (const float*)d_in[4];
    float* out = (float*)d_out;

    cudaFuncSetAttribute(k_main, cudaFuncAttributeMaxDynamicSharedMemorySize, SMEMT);
    cudaFuncSetAttribute(k_proj, cudaFuncAttributeMaxDynamicSharedMemorySize, PROJ_SMEM);

    k_proj<<<NN / 64, 256, PROJ_SMEM>>>(feat, W, a);
    k_max<<<1, 256>>>();
    k_main<<<256, 256, SMEMT>>>(geo, sem);
    k_fin<<<1024, 256>>>(out);
}